// round 16
// baseline (speedup 1.0000x reference)
#include <cuda_runtime.h>
#include <cuda_fp16.h>
#include <cstdint>
#include <math.h>

#define Bb_ 128
#define Tt_ 512
#define Ii_ 1024
#define Hh_ 1024
#define G4_ 4096
#define Cc_ 512

// Scratch (device globals — allocation-free per harness rules)
__device__ uint32_t g_G16[(size_t)Tt_ * Bb_ * 2048];  // gate preacts, fp16x2, permuted n
__device__ float g_ctxg[Bb_ * G4_];                   // ctx@Wc.T + bc + bi + bh (orig n order)
__device__ uint32_t g_h16[2][Bb_ * 512];              // h state, fp16x2, double buffered
__device__ uint32_t g_x16[(size_t)Bb_ * Tt_ * 512];   // x packed fp16x2
__device__ uint32_t g_Wi16[(size_t)G4_ * 512];        // Wi packed, PERMUTED rows
__device__ uint32_t g_Wh16[(size_t)G4_ * 512];        // Wh packed, PERMUTED rows
__device__ unsigned g_cnt2[2];                        // per-bm-group barrier counters
__device__ int g_sense2[2];                           // per-bm-group senses

// permutation: n' = jg*64 + wn*16 + f*8 + tj*2 + e  where n = gate*1024 + j,
// gate = 2f+e, j = jg*16 + wn*4 + tj
__device__ __forceinline__ int n_orig(int np) {
    const int jg = np >> 6, wn = (np >> 4) & 3, f = (np >> 3) & 1, tj = (np >> 1) & 3, e = np & 1;
    return (((f << 1) | e) << 10) | (jg << 4) | (wn << 2) | tj;
}

__device__ __forceinline__ uint32_t pack_h2(float lo, float hi) {
    uint32_t r;
    asm("cvt.rn.f16x2.f32 %0, %1, %2;" : "=r"(r) : "f"(hi), "f"(lo));
    return r;
}

__device__ __forceinline__ uint32_t smem_u32(const void* p) {
    uint32_t a;
    asm("{ .reg .u64 t; cvta.to.shared.u64 t, %1; cvt.u32.u64 %0, t; }" : "=r"(a) : "l"(p));
    return a;
}

__device__ __forceinline__ void cpa16(uint32_t s, const void* g) {
    asm volatile("cp.async.cg.shared.global [%0], [%1], 16;" :: "r"(s), "l"(g));
}

__device__ __forceinline__ void ldsm4(uint32_t* r, uint32_t a) {
    asm volatile("ldmatrix.sync.aligned.m8n8.x4.shared.b16 {%0,%1,%2,%3}, [%4];"
                 : "=r"(r[0]), "=r"(r[1]), "=r"(r[2]), "=r"(r[3]) : "r"(a));
}

__device__ __forceinline__ void mma16h(float* c, const uint32_t* a, const uint32_t* b) {
    asm("mma.sync.aligned.m16n8k16.row.col.f32.f16.f16.f32 "
        "{%0,%1,%2,%3},{%4,%5,%6,%7},{%8,%9},{%0,%1,%2,%3};"
        : "+f"(c[0]), "+f"(c[1]), "+f"(c[2]), "+f"(c[3])
        : "r"(a[0]), "r"(a[1]), "r"(a[2]), "r"(a[3]), "r"(b[0]), "r"(b[1]));
}

// Sense-reversing barrier across the 64 blocks sharing one bm group.
__device__ __forceinline__ void groupbar(int& ls, int grp) {
    const int target = ls ^ 1;
    __syncthreads();
    if (threadIdx.x == 0) {
        __threadfence();
        if (atomicAdd(&g_cnt2[grp], 1u) == 63u) {
            g_cnt2[grp] = 0u;
            asm volatile("st.release.gpu.s32 [%0], %1;" :: "l"(&g_sense2[grp]), "r"(target) : "memory");
        } else {
            int v;
            do {
                asm volatile("ld.acquire.gpu.s32 %0, [%1];" : "=r"(v) : "l"(&g_sense2[grp]) : "memory");
            } while (v != target);
        }
    }
    __syncthreads();
    ls = target;
}

// ---------------------------------------------------------------------------
// fp32 -> fp16x2 pack (x, linear rows)
// ---------------------------------------------------------------------------
__global__ void __launch_bounds__(256) k_cvt(const float* __restrict__ src,
                                             uint32_t* __restrict__ dst) {
    const size_t i = (size_t)blockIdx.x * 256 + threadIdx.x;
    const float4 a = *(const float4*)(src + i * 8);
    const float4 b = *(const float4*)(src + i * 8 + 4);
    uint4 o;
    o.x = pack_h2(a.x, a.y);
    o.y = pack_h2(a.z, a.w);
    o.z = pack_h2(b.x, b.y);
    o.w = pack_h2(b.z, b.w);
    *(uint4*)(dst + i * 4) = o;
}

// fp32 -> fp16x2 pack with row permutation (Wi, Wh). 1 block per output row n'.
__global__ void __launch_bounds__(256) k_cvtp(const float* __restrict__ src,
                                              uint32_t* __restrict__ dst) {
    const int np = blockIdx.x;
    const int n = n_orig(np);
    const float4 v = *(const float4*)(src + (size_t)n * 1024 + threadIdx.x * 4);
    uint2 o;
    o.x = pack_h2(v.x, v.y);
    o.y = pack_h2(v.z, v.w);
    *(uint2*)(dst + (size_t)np * 512 + threadIdx.x * 2) = o;
}

// ---------------------------------------------------------------------------
// Phase 0: ctxg[b][n] = ctx[b]·Wc[n] + bc[n] + bi[n] + bh[n]   (fp32 exact)
// ---------------------------------------------------------------------------
__global__ void __launch_bounds__(256) k_ctxg(const float* __restrict__ ctx,
                                              const float* __restrict__ Wc,
                                              const float* __restrict__ bc,
                                              const float* __restrict__ bi,
                                              const float* __restrict__ bh) {
    __shared__ float cs[8][512];
    const int b0 = blockIdx.y * 8;
    const int n = blockIdx.x * 256 + threadIdx.x;
    for (int i = threadIdx.x; i < 8 * 512; i += 256)
        cs[i >> 9][i & 511] = ctx[(size_t)(b0 + (i >> 9)) * 512 + (i & 511)];
    __syncthreads();

    float acc[8];
#pragma unroll
    for (int r = 0; r < 8; r++) acc[r] = 0.f;

    const float* w = Wc + (size_t)n * 512;
    for (int k4 = 0; k4 < 128; k4++) {
        float4 wv = *(const float4*)(w + (k4 << 2));
#pragma unroll
        for (int r = 0; r < 8; r++) {
            acc[r] += cs[r][k4 * 4 + 0] * wv.x;
            acc[r] += cs[r][k4 * 4 + 1] * wv.y;
            acc[r] += cs[r][k4 * 4 + 2] * wv.z;
            acc[r] += cs[r][k4 * 4 + 3] * wv.w;
        }
    }
    const float bias = bc[n] + bi[n] + bh[n];
#pragma unroll
    for (int r = 0; r < 8; r++)
        g_ctxg[(size_t)(b0 + r) * G4_ + n] = acc[r] + bias;
}

// ---------------------------------------------------------------------------
// Phase 1 (fp16 HMMA + ldmatrix + cp.async 3-stage, K-chunk 64):
// G16[t][b][n'] = fp16(x_row·Wi[n'] + ctxg[b][n'])  (permuted n)
// Block tile 128x128, 128 threads, 4 warps in 2(M)x2(N), warp tile 64x64.
// grid (32, 512). Stages 3 x 32KB = 96KB -> 2 blocks/SM.
// ---------------------------------------------------------------------------
__global__ void __launch_bounds__(128) k_phase1_h(const uint32_t* __restrict__ x16,
                                                  const uint32_t* __restrict__ Wi16) {
    extern __shared__ __align__(16) char smem[];
    const uint32_t sb = smem_u32(smem);

    const int tid = threadIdx.x;
    const int lane = tid & 31, warp = tid >> 5;
    const int wm = warp >> 1, wn = warp & 1;        // 2(M) x 2(N); warp tile 64x64
    const int g = lane >> 2, tg = lane & 3;
    const int sub = lane >> 3, l7 = lane & 7;
    const int m0 = blockIdx.y << 7, n0 = blockIdx.x << 7;

    // ldmatrix geometry (A: 4 m-tiles of 16; B: 4 pairs covering 8 n-tiles of 8)
    const int cselA = (sub >> 1) << 2;
    int aRow16[4], aSw[4];
#pragma unroll
    for (int mt = 0; mt < 4; mt++) {
        const int r = (wm << 6) + (mt << 4) + ((sub & 1) << 3) + l7;
        aRow16[mt] = r << 4;
        aSw[mt] = ((r >> 1) & 3) << 2;
    }
    const int cselB = (sub & 1) << 2;
    int bRow16[4], bSw[4];
#pragma unroll
    for (int p = 0; p < 4; p++) {
        const int r = (wn << 6) + (p << 4) + ((sub >> 1) << 3) + l7;
        bRow16[p] = r << 4;
        bSw[p] = ((r >> 1) & 3) << 2;
    }

    // cp.async geometry: 128 threads; per su sub-block ([128 rows][16 words], 8KB)
    // each thread owns one full row (tid) = 4 cpa16 per su per matrix.
    const int swr = ((tid >> 1) & 3) << 2;
    int dRow[4];
#pragma unroll
    for (int q = 0; q < 4; q++) dRow[q] = (tid * 16 + ((q << 2) ^ swr)) << 2;
    const uint32_t* xrow = x16 + (size_t)(m0 + tid) * 512;
    const uint32_t* wrow = Wi16 + (size_t)(n0 + tid) * 512;

    // Stage layout: stride 32768. A su0 @0, su1 @8192; B su0 @16384, su1 @24576.
    auto issue = [&](int kc) {
        const uint32_t st = sb + (kc % 3) * 32768;
        const int o = kc << 5;
#pragma unroll
        for (int su = 0; su < 2; su++) {
#pragma unroll
            for (int q = 0; q < 4; q++) {
                cpa16(st + (su << 13) + dRow[q], xrow + o + (su << 4) + (q << 2));
                cpa16(st + 16384 + (su << 13) + dRow[q], wrow + o + (su << 4) + (q << 2));
            }
        }
        asm volatile("cp.async.commit_group;" ::: "memory");
    };

    float acc[4][8][4];
#pragma unroll
    for (int a = 0; a < 4; a++)
#pragma unroll
        for (int b2 = 0; b2 < 8; b2++)
#pragma unroll
            for (int c = 0; c < 4; c++) acc[a][b2][c] = 0.f;

    issue(0); issue(1);

    for (int kc = 0; kc < 16; kc++) {
        if (kc < 15) asm volatile("cp.async.wait_group 1;" ::: "memory");
        else         asm volatile("cp.async.wait_group 0;" ::: "memory");
        __syncthreads();
        if (kc + 2 < 16) issue(kc + 2);

        const uint32_t st = sb + (kc % 3) * 32768;
#pragma unroll
        for (int su = 0; su < 2; su++) {
            const uint32_t aB = st + (su << 13);
            const uint32_t bB = st + 16384 + (su << 13);
#pragma unroll
            for (int kk = 0; kk < 2; kk++) {
                const int kbase = kk << 3;
                uint32_t af[4][4], bf[4][4];
#pragma unroll
                for (int mt = 0; mt < 4; mt++)
                    ldsm4(af[mt], aB + ((aRow16[mt] + ((kbase | cselA) ^ aSw[mt])) << 2));
#pragma unroll
                for (int p = 0; p < 4; p++)
                    ldsm4(bf[p], bB + ((bRow16[p] + ((kbase | cselB) ^ bSw[p])) << 2));
#pragma unroll
                for (int mt = 0; mt < 4; mt++)
#pragma unroll
                    for (int nt = 0; nt < 8; nt++)
                        mma16h(acc[mt][nt], af[mt], &bf[nt >> 1][(nt & 1) << 1]);
            }
        }
    }

    // Epilogue: stage permuted ctxg (128 vals), add, pack fp16, store G16.
    __syncthreads();
    float* sc = (float*)smem;
    const int b = m0 >> 9;
    sc[tid] = g_ctxg[(size_t)b * G4_ + n_orig(n0 + tid)];
    __syncthreads();

#pragma unroll
    for (int mt = 0; mt < 4; mt++) {
#pragma unroll
        for (int half = 0; half < 2; half++) {
            const int m = m0 + (wm << 6) + (mt << 4) + g + half * 8;
            const int tt = m & 511;
            uint32_t* grow = g_G16 + ((size_t)tt * Bb_ + b) * 2048;
#pragma unroll
            for (int nt = 0; nt < 8; nt++) {
                const int l0 = (wn << 6) + (nt << 3) + (tg << 1);
                grow[(n0 + l0) >> 1] =
                    pack_h2(acc[mt][nt][half * 2 + 0] + sc[l0],
                            acc[mt][nt][half * 2 + 1] + sc[l0 + 1]);
            }
        }
    }
}

// ---------------------------------------------------------------------------
// Phase 2: persistent recurrence (round-13 known-good). 128 blocks x 256 thr.
// Block (bm, jg): batch rows [bm*64,+64), j-cols [jg*16,+16), all 4 gates.
// Wh slice resident in smem. K-chunk 256 (4 inner barriers/step).
// Per-bm group barriers (64 blocks each). Cell state in registers.
// ---------------------------------------------------------------------------
__global__ void __launch_bounds__(256) k_rec(const float* __restrict__ h0,
                                             const float* __restrict__ c0,
                                             const uint32_t* __restrict__ Wh16,
                                             float* __restrict__ out) {
    extern __shared__ __align__(16) char smem[];
    uint32_t* WhS = (uint32_t*)smem;               // 32768 words (128 KB)
    const uint32_t sb = smem_u32(smem);
    const uint32_t sbA = sb + 131072;              // A stages: 3 x 32 KB

    const int tid = threadIdx.x, lane = tid & 31, warp = tid >> 5;
    const int wm = warp >> 2, wn = warp & 3;        // 2(M) x 4(N)
    const int g = lane >> 2, tg = lane & 3;
    const int sub = lane >> 3, l7 = lane & 7;
    const int bm = blockIdx.x >> 6, jg = blockIdx.x & 63;
    const int b0 = bm << 6;

    int ls = 0;

    // Load resident Wh slice (permuted rows jg*64 .. +64) into smem, swizzled.
    // Layout: 32 sub-blocks (k-32 each) of [64 rows][16 words].
    {
        const int r = tid >> 2, w4i = (tid & 3) << 2;
        const int swr = ((r >> 1) & 3) << 2;
        const uint32_t* src = Wh16 + (size_t)(jg * 64 + r) * 512 + w4i;
        uint32_t* dst = WhS + r * 16 + (w4i ^ swr);
        for (int kc = 0; kc < 32; kc++)
            *(uint4*)(dst + kc * 1024) = *(const uint4*)(src + kc * 16);
    }

    // Stage h0 -> g_h16[0] (this block's rows x its word slice)
    {
        const int r = tid >> 2, fc = (tid & 3) << 2;
        const float4 hv = *(const float4*)(h0 + (size_t)(bm * 64 + r) * 1024 + jg * 16 + fc);
        uint2 o;
        o.x = pack_h2(hv.x, hv.y);
        o.y = pack_h2(hv.z, hv.w);
        *(uint2*)&g_h16[0][(size_t)(bm * 64 + r) * 512 + jg * 8 + (fc >> 1)] = o;
    }

    // Cell state: 4 cells/thread (4 rows x 1 j)
    const int j_ = jg * 16 + (wn << 2) + tg;
    float cst[4];
#pragma unroll
    for (int ci = 0; ci < 4; ci++) {
        const int row = b0 + (wm << 5) + ((ci >> 1) << 4) + g + ((ci & 1) << 3);
        cst[ci] = c0[(size_t)row * 1024 + j_];
    }

    groupbar(ls, bm);   // #1: h0 staged within this bm group

    // ldmatrix geometry
    const int cselA = (sub >> 1) << 2;
    int aRW[2], aSw[2];
#pragma unroll
    for (int mf = 0; mf < 2; mf++) {
        const int r = (wm << 5) + (mf << 4) + ((sub & 1) << 3) + l7;
        aRW[mf] = r << 4;
        aSw[mf] = ((r >> 1) & 3) << 2;
    }
    const int cselB = (sub & 1) << 2;
    const int brr = (wn << 4) + ((sub >> 1) << 3) + l7;
    const int bRW = brr << 4, bSw = ((brr >> 1) & 3) << 2;

    // A cp.async geometry: thread covers row rA, 4-word group w4
    const int rA = tid >> 2, w4 = (tid & 3) << 2;
    const int swA = ((rA >> 1) & 3) << 2;
    const int dAw = rA * 16 + (w4 ^ swA);

    const size_t OUT_F = (size_t)Bb_ * Tt_ * Hh_;

    for (int t = 0; t < Tt_; t++) {
        const uint32_t* hcur = g_h16[t & 1] + (size_t)(b0 + rA) * 512 + w4;

        // prefetch G16 words (independent of h)
        uint32_t gw[2][2][2];
#pragma unroll
        for (int mf = 0; mf < 2; mf++)
#pragma unroll
            for (int e2 = 0; e2 < 2; e2++) {
                const int row = b0 + (wm << 5) + (mf << 4) + g + (e2 << 3);
                const uint32_t* gr = g_G16 + ((size_t)t * Bb_ + row) * 2048
                                    + jg * 32 + (wn << 3) + tg;
#pragma unroll
                for (int nf = 0; nf < 2; nf++) gw[mf][e2][nf] = __ldg(gr + (nf << 2));
            }

        // chunk = 256 k = 128 words; 8 sub-blocks of [64 rows][16 words] (4 KB each)
        auto issue = [&](int kc) {
            const uint32_t st = sbA + (kc % 3) * 32768;
            const uint32_t* src = hcur + (kc << 7);
#pragma unroll
            for (int su = 0; su < 8; su++)
                cpa16(st + (((su << 10) + dAw) << 2), src + (su << 4));
            asm volatile("cp.async.commit_group;" ::: "memory");
        };

        float acc[2][2][4];
#pragma unroll
        for (int a = 0; a < 2; a++)
#pragma unroll
            for (int b2 = 0; b2 < 2; b2++)
#pragma unroll
                for (int c = 0; c < 4; c++) acc[a][b2][c] = 0.f;

        issue(0); issue(1);

        for (int kc = 0; kc < 4; kc++) {
            if (kc < 3) asm volatile("cp.async.wait_group 1;" ::: "memory");
            else        asm volatile("cp.async.wait_group 0;" ::: "memory");
            __syncthreads();
            if (kc + 2 < 4) issue(kc + 2);

            const uint32_t aCh = sbA + (kc % 3) * 32768;
#pragma unroll
            for (int su = 0; su < 8; su++) {
                const uint32_t aB = aCh + (su << 12);
                const uint32_t bKC = sb + (((kc << 3) + su) << 12);
#pragma unroll
                for (int kk = 0; kk < 2; kk++) {
                    const int kbase = kk << 3;
                    uint32_t af[2][4], bf[4];
#pragma unroll
                    for (int mf = 0; mf < 2; mf++)
                        ldsm4(af[mf], aB + ((aRW[mf] + ((kbase | cselA) ^ aSw[mf])) << 2));
                    ldsm4(bf, bKC + ((bRW + ((kbase | cselB) ^ bSw)) << 2));
#pragma unroll
                    for (int mf = 0; mf < 2; mf++) {
                        mma16h(acc[mf][0], af[mf], &bf[0]);
                        mma16h(acc[mf][1], af[mf], &bf[2]);
                    }
                }
            }
        }

        // Epilogue: gates + state + stores (4 cells/thread)
        half* hnext = (half*)&g_h16[(t + 1) & 1][0];
#pragma unroll
        for (int mf = 0; mf < 2; mf++) {
#pragma unroll
            for (int e2 = 0; e2 < 2; e2++) {
                const int ci = (mf << 1) + e2;
                const int row = b0 + (wm << 5) + (mf << 4) + g + (e2 << 3);
                const float2 g01 = __half22float2(*(__half2*)&gw[mf][e2][0]);
                const float2 g23 = __half22float2(*(__half2*)&gw[mf][e2][1]);
                float ig = acc[mf][0][e2 * 2 + 0] + g01.x;
                float fg = acc[mf][0][e2 * 2 + 1] + g01.y;
                float gg = acc[mf][1][e2 * 2 + 0] + g23.x;
                float og = acc[mf][1][e2 * 2 + 1] + g23.y;
                ig = 1.f / (1.f + expf(-ig));
                fg = 1.f / (1.f + expf(-fg));
                gg = tanhf(gg);
                og = 1.f / (1.f + expf(-og));
                const float cn = fg * cst[ci] + ig * gg;
                cst[ci] = cn;
                const float hn = og * tanhf(cn);
                out[((size_t)row * Tt_ + t) * Hh_ + j_] = hn;
                hnext[(size_t)row * 1024 + j_] = __float2half(hn);
                if (t == Tt_ - 1) {
                    out[OUT_F + (size_t)row * Hh_ + j_] = hn;
                    out[OUT_F + (size_t)Bb_ * Hh_ + (size_t)row * Hh_ + j_] = cn;
                }
            }
        }

        if (t < Tt_ - 1) groupbar(ls, bm);   // total 512 flips (even) per group
    }
}

// ---------------------------------------------------------------------------
extern "C" void kernel_launch(void* const* d_in, const int* in_sizes, int n_in,
                              void* d_out, int out_size) {
    (void)in_sizes; (void)n_in; (void)out_size;
    const float* x   = (const float*)d_in[0];
    const float* h0  = (const float*)d_in[1];
    const float* c0  = (const float*)d_in[2];
    const float* ctx = (const float*)d_in[3];
    const float* Wi  = (const float*)d_in[4];
    const float* bi  = (const float*)d_in[5];
    const float* Wh  = (const float*)d_in[6];
    const float* bh  = (const float*)d_in[7];
    const float* Wc  = (const float*)d_in[8];
    const float* bc  = (const float*)d_in[9];
    float* out = (float*)d_out;

    uint32_t* x16p;  cudaGetSymbolAddress((void**)&x16p, g_x16);
    uint32_t* wi16p; cudaGetSymbolAddress((void**)&wi16p, g_Wi16);
    uint32_t* wh16p; cudaGetSymbolAddress((void**)&wh16p, g_Wh16);

    static int inited = 0;
    if (!inited) {
        cudaFuncSetAttribute(k_phase1_h, cudaFuncAttributeMaxDynamicSharedMemorySize, 98304);
        cudaFuncSetAttribute(k_rec, cudaFuncAttributeMaxDynamicSharedMemorySize, 229376);
        inited = 1;
    }

    k_cvt<<<32768, 256>>>(x, x16p);          // 64M floats
    k_cvtp<<<4096, 256>>>(Wi, wi16p);        // permuted rows
    k_cvtp<<<4096, 256>>>(Wh, wh16p);        // permuted rows
    k_ctxg<<<dim3(16, 16), 256>>>(ctx, Wc, bc, bi, bh);
    k_phase1_h<<<dim3(32, 512), 128, 98304>>>(x16p, wi16p);
    k_rec<<<128, 256, 229376>>>(h0, c0, wh16p, out);
}

// round 17
// speedup vs baseline: 1.2066x; 1.2066x over previous
#include <cuda_runtime.h>
#include <cuda_fp16.h>
#include <cstdint>
#include <math.h>

#define Bb_ 128
#define Tt_ 512
#define Ii_ 1024
#define Hh_ 1024
#define G4_ 4096
#define Cc_ 512

// Scratch (device globals — allocation-free per harness rules)
__device__ uint32_t g_G16[(size_t)Tt_ * Bb_ * 2048];  // gate preacts, fp16x2, permuted n
__device__ float g_ctxg[Bb_ * G4_];                   // ctx@Wc.T + bc + bi + bh (orig n order)
__device__ uint32_t g_h16[2][Bb_ * 512];              // h state, fp16x2, double buffered
__device__ uint32_t g_x16[(size_t)Bb_ * Tt_ * 512];   // x packed fp16x2
__device__ uint32_t g_Wi16[(size_t)G4_ * 512];        // Wi packed, PERMUTED rows
__device__ uint32_t g_Wh16[(size_t)G4_ * 512];        // Wh packed, PERMUTED rows
__device__ int g_flags[2 * 64 * 32];                  // distributed barrier flags (128B stride)

// permutation: n' = jg*64 + wn*16 + f*8 + tj*2 + e  where n = gate*1024 + j,
// gate = 2f+e, j = jg*16 + wn*4 + tj
__device__ __forceinline__ int n_orig(int np) {
    const int jg = np >> 6, wn = (np >> 4) & 3, f = (np >> 3) & 1, tj = (np >> 1) & 3, e = np & 1;
    return (((f << 1) | e) << 10) | (jg << 4) | (wn << 2) | tj;
}

__device__ __forceinline__ uint32_t pack_h2(float lo, float hi) {
    uint32_t r;
    asm("cvt.rn.f16x2.f32 %0, %1, %2;" : "=r"(r) : "f"(hi), "f"(lo));
    return r;
}

__device__ __forceinline__ uint32_t smem_u32(const void* p) {
    uint32_t a;
    asm("{ .reg .u64 t; cvta.to.shared.u64 t, %1; cvt.u32.u64 %0, t; }" : "=r"(a) : "l"(p));
    return a;
}

__device__ __forceinline__ void cpa16(uint32_t s, const void* g) {
    asm volatile("cp.async.cg.shared.global [%0], [%1], 16;" :: "r"(s), "l"(g));
}

__device__ __forceinline__ void ldsm4(uint32_t* r, uint32_t a) {
    asm volatile("ldmatrix.sync.aligned.m8n8.x4.shared.b16 {%0,%1,%2,%3}, [%4];"
                 : "=r"(r[0]), "=r"(r[1]), "=r"(r[2]), "=r"(r[3]) : "r"(a));
}

__device__ __forceinline__ void mma16h(float* c, const uint32_t* a, const uint32_t* b) {
    asm("mma.sync.aligned.m16n8k16.row.col.f32.f16.f16.f32 "
        "{%0,%1,%2,%3},{%4,%5,%6,%7},{%8,%9},{%0,%1,%2,%3};"
        : "+f"(c[0]), "+f"(c[1]), "+f"(c[2]), "+f"(c[3])
        : "r"(a[0]), "r"(a[1]), "r"(a[2]), "r"(a[3]), "r"(b[0]), "r"(b[1]));
}

// Fast gates via MUFU.EX2-based __expf (rel err ~1e-6, safe vs 1e-3 budget)
__device__ __forceinline__ float sigm_f(float x) {
    return __fdividef(1.f, 1.f + __expf(-x));
}
__device__ __forceinline__ float tanh_f(float x) {
    return 1.f - __fdividef(2.f, 1.f + __expf(2.f * x));
}

// ---------------------------------------------------------------------------
// fp32 -> fp16x2 pack (x, linear rows)
// ---------------------------------------------------------------------------
__global__ void __launch_bounds__(256) k_cvt(const float* __restrict__ src,
                                             uint32_t* __restrict__ dst) {
    const size_t i = (size_t)blockIdx.x * 256 + threadIdx.x;
    const float4 a = *(const float4*)(src + i * 8);
    const float4 b = *(const float4*)(src + i * 8 + 4);
    uint4 o;
    o.x = pack_h2(a.x, a.y);
    o.y = pack_h2(a.z, a.w);
    o.z = pack_h2(b.x, b.y);
    o.w = pack_h2(b.z, b.w);
    *(uint4*)(dst + i * 4) = o;
}

// fp32 -> fp16x2 pack with row permutation (Wi, Wh). 1 block per output row n'.
__global__ void __launch_bounds__(256) k_cvtp(const float* __restrict__ src,
                                              uint32_t* __restrict__ dst) {
    const int np = blockIdx.x;
    const int n = n_orig(np);
    const float4 v = *(const float4*)(src + (size_t)n * 1024 + threadIdx.x * 4);
    uint2 o;
    o.x = pack_h2(v.x, v.y);
    o.y = pack_h2(v.z, v.w);
    *(uint2*)(dst + (size_t)np * 512 + threadIdx.x * 2) = o;
}

// Zero barrier flags (run before k_rec each launch -> replay-deterministic)
__global__ void __launch_bounds__(256) k_zero() {
    for (int i = threadIdx.x; i < 2 * 64 * 32; i += 256) g_flags[i] = 0;
}

// ---------------------------------------------------------------------------
// Phase 0: ctxg[b][n] = ctx[b]·Wc[n] + bc[n] + bi[n] + bh[n]   (fp32 exact)
// ---------------------------------------------------------------------------
__global__ void __launch_bounds__(256) k_ctxg(const float* __restrict__ ctx,
                                              const float* __restrict__ Wc,
                                              const float* __restrict__ bc,
                                              const float* __restrict__ bi,
                                              const float* __restrict__ bh) {
    __shared__ float cs[8][512];
    const int b0 = blockIdx.y * 8;
    const int n = blockIdx.x * 256 + threadIdx.x;
    for (int i = threadIdx.x; i < 8 * 512; i += 256)
        cs[i >> 9][i & 511] = ctx[(size_t)(b0 + (i >> 9)) * 512 + (i & 511)];
    __syncthreads();

    float acc[8];
#pragma unroll
    for (int r = 0; r < 8; r++) acc[r] = 0.f;

    const float* w = Wc + (size_t)n * 512;
    for (int k4 = 0; k4 < 128; k4++) {
        float4 wv = *(const float4*)(w + (k4 << 2));
#pragma unroll
        for (int r = 0; r < 8; r++) {
            acc[r] += cs[r][k4 * 4 + 0] * wv.x;
            acc[r] += cs[r][k4 * 4 + 1] * wv.y;
            acc[r] += cs[r][k4 * 4 + 2] * wv.z;
            acc[r] += cs[r][k4 * 4 + 3] * wv.w;
        }
    }
    const float bias = bc[n] + bi[n] + bh[n];
#pragma unroll
    for (int r = 0; r < 8; r++)
        g_ctxg[(size_t)(b0 + r) * G4_ + n] = acc[r] + bias;
}

// ---------------------------------------------------------------------------
// Phase 1 (fp16 HMMA + ldmatrix + cp.async 3-stage, K-chunk 64):
// G16[t][b][n'] = fp16(x_row·Wi[n'] + ctxg[b][n'])  (permuted n)
// 128x128 block tile, 256 threads, warp tile 64x32. grid (32, 512).
// Stages: A 3x16KB @0, B 3x16KB @49152. 2 blocks/SM. (round-13 known-good)
// ---------------------------------------------------------------------------
__global__ void __launch_bounds__(256) k_phase1_h(const uint32_t* __restrict__ x16,
                                                  const uint32_t* __restrict__ Wi16) {
    extern __shared__ __align__(16) char smem[];
    const uint32_t sb = smem_u32(smem);

    const int tid = threadIdx.x;
    const int lane = tid & 31, warp = tid >> 5;
    const int wm = warp >> 2, wn = warp & 3;        // 2(M) x 4(N); warp tile 64x32
    const int g = lane >> 2, tg = lane & 3;
    const int sub = lane >> 3, l7 = lane & 7;
    const int m0 = blockIdx.y << 7, n0 = blockIdx.x << 7;

    // ldmatrix geometry
    const int cselA = (sub >> 1) << 2;
    int aRow16[4], aSw[4];
#pragma unroll
    for (int mt = 0; mt < 4; mt++) {
        const int r = (wm << 6) + (mt << 4) + ((sub & 1) << 3) + l7;
        aRow16[mt] = r << 4;
        aSw[mt] = ((r >> 1) & 3) << 2;
    }
    const int cselB = (sub & 1) << 2;
    int bRow16[2], bSw[2];
#pragma unroll
    for (int p = 0; p < 2; p++) {
        const int r = (wn << 5) + (p << 4) + ((sub >> 1) << 3) + l7;
        bRow16[p] = r << 4;
        bSw[p] = ((r >> 1) & 3) << 2;
    }

    // cp.async geometry: r = tid>>1 (128 rows), 8-word half select
    const int lr = tid >> 1, w8 = (tid & 1) << 3;
    const int lsw = ((lr >> 1) & 3) << 2;
    const int dA0 = (lr * 16 + (w8 ^ lsw)) << 2;
    const int dA1 = (lr * 16 + ((w8 + 4) ^ lsw)) << 2;
    const uint32_t* xrow = x16 + (size_t)(m0 + lr) * 512 + w8;
    const uint32_t* wrow = Wi16 + (size_t)(n0 + lr) * 512 + w8;

    // chunk = 64 k = 32 words; laid out as 2 sub-blocks of [128 rows][16 words]
    auto issue = [&](int kc) {
        const int s = kc % 3;
        const uint32_t aBase = sb + s * 16384;
        const uint32_t bBase = sb + 49152 + s * 16384;
        const int o = kc << 5;
#pragma unroll
        for (int su = 0; su < 2; su++) {
            cpa16(aBase + (su << 13) + dA0, xrow + o + (su << 4));
            cpa16(aBase + (su << 13) + dA1, xrow + o + (su << 4) + 4);
            cpa16(bBase + (su << 13) + dA0, wrow + o + (su << 4));
            cpa16(bBase + (su << 13) + dA1, wrow + o + (su << 4) + 4);
        }
        asm volatile("cp.async.commit_group;" ::: "memory");
    };

    float acc[4][4][4];
#pragma unroll
    for (int a = 0; a < 4; a++)
#pragma unroll
        for (int b2 = 0; b2 < 4; b2++)
#pragma unroll
            for (int c = 0; c < 4; c++) acc[a][b2][c] = 0.f;

    issue(0); issue(1);

    for (int kc = 0; kc < 16; kc++) {
        if (kc < 15) asm volatile("cp.async.wait_group 1;" ::: "memory");
        else         asm volatile("cp.async.wait_group 0;" ::: "memory");
        __syncthreads();
        if (kc + 2 < 16) issue(kc + 2);

        const int s = kc % 3;
#pragma unroll
        for (int su = 0; su < 2; su++) {
            const uint32_t aB = sb + s * 16384 + (su << 13);
            const uint32_t bB = sb + 49152 + s * 16384 + (su << 13);
#pragma unroll
            for (int kk = 0; kk < 2; kk++) {
                const int kbase = kk << 3;
                uint32_t af[4][4], bf[2][4];
#pragma unroll
                for (int mt = 0; mt < 4; mt++)
                    ldsm4(af[mt], aB + ((aRow16[mt] + ((kbase | cselA) ^ aSw[mt])) << 2));
#pragma unroll
                for (int p = 0; p < 2; p++)
                    ldsm4(bf[p], bB + ((bRow16[p] + ((kbase | cselB) ^ bSw[p])) << 2));
#pragma unroll
                for (int mt = 0; mt < 4; mt++)
#pragma unroll
                    for (int nt = 0; nt < 4; nt++)
                        mma16h(acc[mt][nt], af[mt], &bf[nt >> 1][(nt & 1) << 1]);
            }
        }
    }

    // Epilogue: stage permuted ctxg, add, pack fp16, store G16.
    __syncthreads();
    float* sc = (float*)smem;
    const int b = m0 >> 9;
    if (tid < 128) sc[tid] = g_ctxg[(size_t)b * G4_ + n_orig(n0 + tid)];
    __syncthreads();

#pragma unroll
    for (int mt = 0; mt < 4; mt++) {
#pragma unroll
        for (int half = 0; half < 2; half++) {
            const int m = m0 + (wm << 6) + (mt << 4) + g + half * 8;
            const int tt = m & 511;
            uint32_t* grow = g_G16 + ((size_t)tt * Bb_ + b) * 2048;
#pragma unroll
            for (int nt = 0; nt < 4; nt++) {
                const int l0 = (wn << 5) + (nt << 3) + (tg << 1);
                grow[(n0 + l0) >> 1] =
                    pack_h2(acc[mt][nt][half * 2 + 0] + sc[l0],
                            acc[mt][nt][half * 2 + 1] + sc[l0 + 1]);
            }
        }
    }
}

// ---------------------------------------------------------------------------
// Phase 2: persistent recurrence. 128 blocks x 256 threads.
// Block (bm, jg): batch rows [bm*64,+64), j-cols [jg*16,+16), all 4 gates.
// Wh slice resident in smem. K-chunk 256 (4 inner barriers/step).
// Distributed-flag group barrier (no atomic chain). Cell state in registers.
// ---------------------------------------------------------------------------
__global__ void __launch_bounds__(256) k_rec(const float* __restrict__ h0,
                                             const float* __restrict__ c0,
                                             const uint32_t* __restrict__ Wh16,
                                             float* __restrict__ out) {
    extern __shared__ __align__(16) char smem[];
    uint32_t* WhS = (uint32_t*)smem;               // 32768 words (128 KB)
    const uint32_t sb = smem_u32(smem);
    const uint32_t sbA = sb + 131072;              // A stages: 3 x 32 KB

    const int tid = threadIdx.x, lane = tid & 31, warp = tid >> 5;
    const int wm = warp >> 2, wn = warp & 3;        // 2(M) x 4(N)
    const int g = lane >> 2, tg = lane & 3;
    const int sub = lane >> 3, l7 = lane & 7;
    const int bm = blockIdx.x >> 6, jg = blockIdx.x & 63;
    const int b0 = bm << 6;

    int* myflag = &g_flags[(bm << 11) + (jg << 5)];
    int* peerflag = &g_flags[(bm << 11) + (tid << 5)];   // valid for tid < 64

    // Distributed flag barrier: store own step-count, poll 64 peer flags in
    // parallel (one thread per peer, distinct cache lines; no atomic chain).
    auto flagbar = [&](int s) {   // s = barrier sequence number (0-based)
        __syncthreads();
        if (tid == 0)
            asm volatile("st.release.gpu.s32 [%0], %1;" :: "l"(myflag), "r"(s + 1) : "memory");
        if (tid < 64) {
            int v;
            do {
                asm volatile("ld.acquire.gpu.s32 %0, [%1];" : "=r"(v) : "l"(peerflag) : "memory");
            } while (v < s + 1);
        }
        __syncthreads();
    };

    // Load resident Wh slice (permuted rows jg*64 .. +64) into smem, swizzled.
    // Layout: 32 sub-blocks (k-32 each) of [64 rows][16 words].
    {
        const int r = tid >> 2, w4i = (tid & 3) << 2;
        const int swr = ((r >> 1) & 3) << 2;
        const uint32_t* src = Wh16 + (size_t)(jg * 64 + r) * 512 + w4i;
        uint32_t* dst = WhS + r * 16 + (w4i ^ swr);
        for (int kc = 0; kc < 32; kc++)
            *(uint4*)(dst + kc * 1024) = *(const uint4*)(src + kc * 16);
    }

    // Stage h0 -> g_h16[0] (this block's rows x its word slice)
    {
        const int r = tid >> 2, fc = (tid & 3) << 2;
        const float4 hv = *(const float4*)(h0 + (size_t)(bm * 64 + r) * 1024 + jg * 16 + fc);
        uint2 o;
        o.x = pack_h2(hv.x, hv.y);
        o.y = pack_h2(hv.z, hv.w);
        *(uint2*)&g_h16[0][(size_t)(bm * 64 + r) * 512 + jg * 8 + (fc >> 1)] = o;
    }

    // Cell state: 4 cells/thread (4 rows x 1 j)
    const int j_ = jg * 16 + (wn << 2) + tg;
    float cst[4];
#pragma unroll
    for (int ci = 0; ci < 4; ci++) {
        const int row = b0 + (wm << 5) + ((ci >> 1) << 4) + g + ((ci & 1) << 3);
        cst[ci] = c0[(size_t)row * 1024 + j_];
    }

    flagbar(0);   // h0 staged within this bm group

    // ldmatrix geometry
    const int cselA = (sub >> 1) << 2;
    int aRW[2], aSw[2];
#pragma unroll
    for (int mf = 0; mf < 2; mf++) {
        const int r = (wm << 5) + (mf << 4) + ((sub & 1) << 3) + l7;
        aRW[mf] = r << 4;
        aSw[mf] = ((r >> 1) & 3) << 2;
    }
    const int cselB = (sub & 1) << 2;
    const int brr = (wn << 4) + ((sub >> 1) << 3) + l7;
    const int bRW = brr << 4, bSw = ((brr >> 1) & 3) << 2;

    // A cp.async geometry: thread covers row rA, 4-word group w4
    const int rA = tid >> 2, w4 = (tid & 3) << 2;
    const int swA = ((rA >> 1) & 3) << 2;
    const int dAw = rA * 16 + (w4 ^ swA);

    const size_t OUT_F = (size_t)Bb_ * Tt_ * Hh_;

    for (int t = 0; t < Tt_; t++) {
        const uint32_t* hcur = g_h16[t & 1] + (size_t)(b0 + rA) * 512 + w4;

        // prefetch G16 words (independent of h)
        uint32_t gw[2][2][2];
#pragma unroll
        for (int mf = 0; mf < 2; mf++)
#pragma unroll
            for (int e2 = 0; e2 < 2; e2++) {
                const int row = b0 + (wm << 5) + (mf << 4) + g + (e2 << 3);
                const uint32_t* gr = g_G16 + ((size_t)t * Bb_ + row) * 2048
                                    + jg * 32 + (wn << 3) + tg;
#pragma unroll
                for (int nf = 0; nf < 2; nf++) gw[mf][e2][nf] = __ldg(gr + (nf << 2));
            }

        // chunk = 256 k = 128 words; 8 sub-blocks of [64 rows][16 words] (4 KB each)
        auto issue = [&](int kc) {
            const uint32_t st = sbA + (kc % 3) * 32768;
            const uint32_t* src = hcur + (kc << 7);
#pragma unroll
            for (int su = 0; su < 8; su++)
                cpa16(st + (((su << 10) + dAw) << 2), src + (su << 4));
            asm volatile("cp.async.commit_group;" ::: "memory");
        };

        float acc[2][2][4];
#pragma unroll
        for (int a = 0; a < 2; a++)
#pragma unroll
            for (int b2 = 0; b2 < 2; b2++)
#pragma unroll
                for (int c = 0; c < 4; c++) acc[a][b2][c] = 0.f;

        issue(0); issue(1);

        for (int kc = 0; kc < 4; kc++) {
            if (kc < 3) asm volatile("cp.async.wait_group 1;" ::: "memory");
            else        asm volatile("cp.async.wait_group 0;" ::: "memory");
            __syncthreads();
            if (kc + 2 < 4) issue(kc + 2);

            const uint32_t aCh = sbA + (kc % 3) * 32768;
#pragma unroll
            for (int su = 0; su < 8; su++) {
                const uint32_t aB = aCh + (su << 12);
                const uint32_t bKC = sb + (((kc << 3) + su) << 12);
#pragma unroll
                for (int kk = 0; kk < 2; kk++) {
                    const int kbase = kk << 3;
                    uint32_t af[2][4], bf[4];
#pragma unroll
                    for (int mf = 0; mf < 2; mf++)
                        ldsm4(af[mf], aB + ((aRW[mf] + ((kbase | cselA) ^ aSw[mf])) << 2));
                    ldsm4(bf, bKC + ((bRW + ((kbase | cselB) ^ bSw)) << 2));
#pragma unroll
                    for (int mf = 0; mf < 2; mf++) {
                        mma16h(acc[mf][0], af[mf], &bf[0]);
                        mma16h(acc[mf][1], af[mf], &bf[2]);
                    }
                }
            }
        }

        // Epilogue: gates + state + stores (4 cells/thread)
        half* hnext = (half*)&g_h16[(t + 1) & 1][0];
#pragma unroll
        for (int mf = 0; mf < 2; mf++) {
#pragma unroll
            for (int e2 = 0; e2 < 2; e2++) {
                const int ci = (mf << 1) + e2;
                const int row = b0 + (wm << 5) + (mf << 4) + g + (e2 << 3);
                const float2 g01 = __half22float2(*(__half2*)&gw[mf][e2][0]);
                const float2 g23 = __half22float2(*(__half2*)&gw[mf][e2][1]);
                const float ig = sigm_f(acc[mf][0][e2 * 2 + 0] + g01.x);
                const float fg = sigm_f(acc[mf][0][e2 * 2 + 1] + g01.y);
                const float gg = tanh_f(acc[mf][1][e2 * 2 + 0] + g23.x);
                const float og = sigm_f(acc[mf][1][e2 * 2 + 1] + g23.y);
                const float cn = fg * cst[ci] + ig * gg;
                cst[ci] = cn;
                const float hn = og * tanh_f(cn);
                out[((size_t)row * Tt_ + t) * Hh_ + j_] = hn;
                hnext[(size_t)row * 1024 + j_] = __float2half(hn);
                if (t == Tt_ - 1) {
                    out[OUT_F + (size_t)row * Hh_ + j_] = hn;
                    out[OUT_F + (size_t)Bb_ * Hh_ + (size_t)row * Hh_ + j_] = cn;
                }
            }
        }

        if (t < Tt_ - 1) flagbar(t + 1);   // barriers 1..511 (+ initial #0)
    }
}

// ---------------------------------------------------------------------------
extern "C" void kernel_launch(void* const* d_in, const int* in_sizes, int n_in,
                              void* d_out, int out_size) {
    (void)in_sizes; (void)n_in; (void)out_size;
    const float* x   = (const float*)d_in[0];
    const float* h0  = (const float*)d_in[1];
    const float* c0  = (const float*)d_in[2];
    const float* ctx = (const float*)d_in[3];
    const float* Wi  = (const float*)d_in[4];
    const float* bi  = (const float*)d_in[5];
    const float* Wh  = (const float*)d_in[6];
    const float* bh  = (const float*)d_in[7];
    const float* Wc  = (const float*)d_in[8];
    const float* bc  = (const float*)d_in[9];
    float* out = (float*)d_out;

    uint32_t* x16p;  cudaGetSymbolAddress((void**)&x16p, g_x16);
    uint32_t* wi16p; cudaGetSymbolAddress((void**)&wi16p, g_Wi16);
    uint32_t* wh16p; cudaGetSymbolAddress((void**)&wh16p, g_Wh16);

    static int inited = 0;
    if (!inited) {
        cudaFuncSetAttribute(k_phase1_h, cudaFuncAttributeMaxDynamicSharedMemorySize, 98304);
        cudaFuncSetAttribute(k_rec, cudaFuncAttributeMaxDynamicSharedMemorySize, 229376);
        inited = 1;
    }

    k_zero<<<1, 256>>>();                    // reset barrier flags (replay-safe)
    k_cvt<<<32768, 256>>>(x, x16p);          // 64M floats
    k_cvtp<<<4096, 256>>>(Wi, wi16p);        // permuted rows
    k_cvtp<<<4096, 256>>>(Wh, wh16p);        // permuted rows
    k_ctxg<<<dim3(16, 16), 256>>>(ctx, Wc, bc, bi, bh);
    k_phase1_h<<<dim3(32, 512), 256, 98304>>>(x16p, wi16p);
    k_rec<<<128, 256, 229376>>>(h0, c0, wh16p, out);
}